// round 4
// baseline (speedup 1.0000x reference)
#include <cuda_runtime.h>
#include <math.h>

// Problem constants
#define BSZ 8
#define LEN 4096
#define HD  512          // H
#define PD  256          // P
#define BL  (BSZ * LEN)  // 32768 rows
#define K2P 512          // 2*P (re block | im block)
#define NC  64           // scan chunks per sequence
#define CL  (LEN / NC)   // 64 steps per chunk

// ---------------- device scratch (no cudaMalloc allowed) ----------------
__device__ float g_W1[K2P * HD];                 // [2P][H]: rows 0..P-1 = Re(B_bar), P..2P-1 = Im(B_bar)
__device__ float g_W2[HD * K2P];                 // [H][2P]: [h][p]=2*C_re, [h][P+p]=-2*C_im
__device__ float g_Lam[2 * PD];                  // Lambda_bar (re, im) per p
__device__ float g_Bu[(size_t)BL * K2P];         // (BL, 2P)  64 MB
__device__ float g_XS[(size_t)BL * K2P];         // (BL, 2P)  64 MB
__device__ float g_csum[BSZ * NC * PD * 2];      // chunk summaries
__device__ float g_carry[BSZ * NC * PD * 2];     // chunk input carries

// ---------------- setup: discretization + weight packing ----------------
__global__ void setup_kernel(const float* __restrict__ Lre, const float* __restrict__ Lim,
                             const float* __restrict__ Bw,  const float* __restrict__ Cw,
                             const float* __restrict__ logstep) {
    int idx = blockIdx.x * blockDim.x + threadIdx.x;
    if (idx >= PD * HD) return;
    int p = idx / HD, h = idx % HD;

    float lre = Lre[p], lim = Lim[p];
    float step = expf(logstep[p]);
    float ar = lre * step, ai = lim * step;
    float er = expf(ar);
    float sb, cb; sincosf(ai, &sb, &cb);
    float lam_re = er * cb, lam_im = er * sb;          // Lambda_bar

    // coef = (Lambda_bar - 1) / Lambda
    float nr = lam_re - 1.0f, ni = lam_im;
    float d2 = lre * lre + lim * lim;
    float cr = (nr * lre + ni * lim) / d2;
    float ci = (ni * lre - nr * lim) / d2;

    float br = Bw[(p * HD + h) * 2 + 0];
    float bi = Bw[(p * HD + h) * 2 + 1];
    g_W1[p * HD + h]        = cr * br - ci * bi;       // Re(B_bar)
    g_W1[(PD + p) * HD + h] = cr * bi + ci * br;       // Im(B_bar)

    g_W2[h * K2P + p]      =  2.0f * Cw[(h * PD + p) * 2 + 0];
    g_W2[h * K2P + PD + p] = -2.0f * Cw[(h * PD + p) * 2 + 1];

    if (h == 0) { g_Lam[2 * p] = lam_re; g_Lam[2 * p + 1] = lam_im; }
}

// ---------------- fp32 tiled SGEMM, C = A(MxK,row) * W(NxK,row)^T ----------------
#define BM 128
#define BN 64
#define BKK 16
#define TM 8
#define TN 4

__device__ __forceinline__ float gelu_tanh(float x) {
    float x3 = x * x * x;
    float t  = tanhf(0.7978845608028654f * (x + 0.044715f * x3));
    return 0.5f * x * (1.0f + t);
}

template <bool EPI>
__global__ void __launch_bounds__(256) sgemm_nt(const float* __restrict__ A,
                                                const float* __restrict__ W,
                                                float* __restrict__ C,
                                                const float* __restrict__ U,
                                                const float* __restrict__ Dv) {
    const int K = 512, N = 512;
    __shared__ float As[BKK][BM];
    __shared__ float Bs[BKK][BN];

    int tid = threadIdx.x;
    int tx = tid & 15;        // n direction: 16 * TN = 64
    int ty = tid >> 4;        // m direction: 16 * TM = 128
    int m0 = blockIdx.y * BM;
    int n0 = blockIdx.x * BN;

    float acc[TM][TN];
#pragma unroll
    for (int i = 0; i < TM; i++)
#pragma unroll
        for (int j = 0; j < TN; j++) acc[i][j] = 0.0f;

    for (int k0 = 0; k0 < K; k0 += BKK) {
        // A tile: 128x16 = 512 float4, 2 per thread
#pragma unroll
        for (int i = 0; i < 2; i++) {
            int la = tid * 2 + i;
            int r = la >> 2;            // 0..127
            int c4 = (la & 3) * 4;      // 0,4,8,12
            float4 v = *(const float4*)&A[(size_t)(m0 + r) * K + k0 + c4];
            As[c4 + 0][r] = v.x; As[c4 + 1][r] = v.y;
            As[c4 + 2][r] = v.z; As[c4 + 3][r] = v.w;
        }
        // W tile: 64x16 = 256 float4, 1 per thread
        {
            int r = tid >> 2;           // 0..63
            int c4 = (tid & 3) * 4;
            float4 v = *(const float4*)&W[(size_t)(n0 + r) * K + k0 + c4];
            Bs[c4 + 0][r] = v.x; Bs[c4 + 1][r] = v.y;
            Bs[c4 + 2][r] = v.z; Bs[c4 + 3][r] = v.w;
        }
        __syncthreads();

#pragma unroll
        for (int kk = 0; kk < BKK; kk++) {
            float rA[TM], rB[TN];
            *(float4*)&rA[0] = *(const float4*)&As[kk][ty * TM];
            *(float4*)&rA[4] = *(const float4*)&As[kk][ty * TM + 4];
            *(float4*)&rB[0] = *(const float4*)&Bs[kk][tx * TN];
#pragma unroll
            for (int i = 0; i < TM; i++)
#pragma unroll
                for (int j = 0; j < TN; j++)
                    acc[i][j] += rA[i] * rB[j];
        }
        __syncthreads();
    }

#pragma unroll
    for (int i = 0; i < TM; i++) {
        int m = m0 + ty * TM + i;
        int n = n0 + tx * TN;
        float4 r = *(float4*)&acc[i][0];
        if (EPI) {
            float4 uu = *(const float4*)&U[(size_t)m * N + n];
            float4 dd = *(const float4*)&Dv[n];
            r.x = gelu_tanh(r.x + dd.x * uu.x);
            r.y = gelu_tanh(r.y + dd.y * uu.y);
            r.z = gelu_tanh(r.z + dd.z * uu.z);
            r.w = gelu_tanh(r.w + dd.w * uu.w);
        }
        *(float4*)&C[(size_t)m * N + n] = r;
    }
}

// ---------------- chunked scan over L ----------------
// x_l = lam * x_{l-1} + Bu_l  (complex, lam constant per p)
__global__ void __launch_bounds__(PD) scan_pass1() {
    int p  = threadIdx.x;                 // 0..255
    int bc = blockIdx.x;                  // b*NC + c
    int b = bc / NC, c = bc % NC;
    float lr = g_Lam[2 * p], li = g_Lam[2 * p + 1];
    float sr = 0.0f, si = 0.0f;
    size_t base = ((size_t)b * LEN + (size_t)c * CL) * K2P + p;
#pragma unroll 8
    for (int j = 0; j < CL; j++) {
        float br = g_Bu[base + (size_t)j * K2P];
        float bi = g_Bu[base + (size_t)j * K2P + PD];
        float nr = lr * sr - li * si + br;
        float ni = lr * si + li * sr + bi;
        sr = nr; si = ni;
    }
    int idx = (bc * PD + p) * 2;
    g_csum[idx] = sr; g_csum[idx + 1] = si;
}

__global__ void scan_pass2() {
    int t = blockIdx.x * blockDim.x + threadIdx.x;   // 0..2047
    if (t >= BSZ * PD) return;
    int b = t / PD, p = t % PD;
    float lr = g_Lam[2 * p], li = g_Lam[2 * p + 1];
    // lam^CL
    float ar = 1.0f, ai = 0.0f;
    for (int i = 0; i < CL; i++) {
        float nr = ar * lr - ai * li;
        ai = ar * li + ai * lr; ar = nr;
    }
    float cr = 0.0f, ci = 0.0f;
    for (int c = 0; c < NC; c++) {
        int idx = ((b * NC + c) * PD + p) * 2;
        g_carry[idx] = cr; g_carry[idx + 1] = ci;
        float sr = g_csum[idx], si = g_csum[idx + 1];
        float nr = ar * cr - ai * ci + sr;
        float ni = ar * ci + ai * cr + si;
        cr = nr; ci = ni;
    }
}

__global__ void __launch_bounds__(PD) scan_pass3() {
    int p  = threadIdx.x;
    int bc = blockIdx.x;
    int b = bc / NC, c = bc % NC;
    float lr = g_Lam[2 * p], li = g_Lam[2 * p + 1];
    int cidx = (bc * PD + p) * 2;
    float xr = g_carry[cidx], xi = g_carry[cidx + 1];
    size_t base = ((size_t)b * LEN + (size_t)c * CL) * K2P + p;
#pragma unroll 4
    for (int j = 0; j < CL; j++) {
        float br = g_Bu[base + (size_t)j * K2P];
        float bi = g_Bu[base + (size_t)j * K2P + PD];
        float nr = lr * xr - li * xi + br;
        float ni = lr * xi + li * xr + bi;
        xr = nr; xi = ni;
        g_XS[base + (size_t)j * K2P]      = xr;
        g_XS[base + (size_t)j * K2P + PD] = xi;
    }
}

// ---------------- launch ----------------
extern "C" void kernel_launch(void* const* d_in, const int* in_sizes, int n_in,
                              void* d_out, int out_size) {
    const float* u   = (const float*)d_in[0];
    const float* Lre = (const float*)d_in[1];
    const float* Lim = (const float*)d_in[2];
    const float* Bw  = (const float*)d_in[3];
    const float* Cw  = (const float*)d_in[4];
    const float* Dv  = (const float*)d_in[5];
    const float* ls  = (const float*)d_in[6];
    float* out = (float*)d_out;

    void *pW1, *pW2, *pBu, *pXS;
    cudaGetSymbolAddress(&pW1, g_W1);
    cudaGetSymbolAddress(&pW2, g_W2);
    cudaGetSymbolAddress(&pBu, g_Bu);
    cudaGetSymbolAddress(&pXS, g_XS);

    setup_kernel<<<(PD * HD + 255) / 256, 256>>>(Lre, Lim, Bw, Cw, ls);

    dim3 ggrid(K2P / BN, BL / BM);   // (8, 256)
    sgemm_nt<false><<<ggrid, 256>>>(u, (const float*)pW1, (float*)pBu, nullptr, nullptr);

    scan_pass1<<<BSZ * NC, PD>>>();
    scan_pass2<<<(BSZ * PD + 255) / 256, 256>>>();
    scan_pass3<<<BSZ * NC, PD>>>();

    sgemm_nt<true><<<ggrid, 256>>>((const float*)pXS, (const float*)pW2, out, u, Dv);
}

// round 7
// speedup vs baseline: 3.2442x; 3.2442x over previous
#include <cuda_runtime.h>
#include <math.h>
#include <stdint.h>

// Problem constants
#define BSZ 8
#define LEN 4096
#define HD  512          // H
#define PD  256          // P
#define BL  (BSZ * LEN)  // 32768 rows
#define K2P 512          // 2*P (re block | im block)
#define NC  64           // scan chunks per sequence
#define CL  (LEN / NC)   // 64 steps per chunk

// ---------------- device scratch (no cudaMalloc allowed) ----------------
__device__ float g_W1[K2P * HD];                 // [2P][H]: Re(B_bar) rows 0..P-1, Im rows P..2P-1
__device__ float g_W2[HD * K2P];                 // [H][2P]: 2*C_re | -2*C_im
__device__ float g_Lam[2 * PD];                  // Lambda_bar (re, im)
__device__ float g_Bu[(size_t)BL * K2P];         // (BL, 2P)
__device__ float g_XS[(size_t)BL * K2P];         // (BL, 2P)
__device__ float g_csum[BSZ * NC * PD * 2];
__device__ float g_carry[BSZ * NC * PD * 2];

__device__ __forceinline__ uint32_t f2tf32(float v) {
    uint32_t r;
    asm("cvt.rna.tf32.f32 %0, %1;" : "=r"(r) : "f"(v));
    return r;
}

// ---------------- setup: discretization + weight packing ----------------
__global__ void setup_kernel(const float* __restrict__ Lre, const float* __restrict__ Lim,
                             const float* __restrict__ Bw,  const float* __restrict__ Cw,
                             const float* __restrict__ logstep) {
    int idx = blockIdx.x * blockDim.x + threadIdx.x;
    if (idx >= PD * HD) return;
    int p = idx / HD, h = idx % HD;

    float lre = Lre[p], lim = Lim[p];
    float step = expf(logstep[p]);
    float er = expf(lre * step);
    float sb, cb; sincosf(lim * step, &sb, &cb);
    float lam_re = er * cb, lam_im = er * sb;          // Lambda_bar

    float nr = lam_re - 1.0f, ni = lam_im;
    float d2 = lre * lre + lim * lim;
    float cr = (nr * lre + ni * lim) / d2;
    float ci = (ni * lre - nr * lim) / d2;

    float br = Bw[(p * HD + h) * 2 + 0];
    float bi = Bw[(p * HD + h) * 2 + 1];
    g_W1[p * HD + h]        = cr * br - ci * bi;       // Re(B_bar)
    g_W1[(PD + p) * HD + h] = cr * bi + ci * br;       // Im(B_bar)

    g_W2[h * K2P + p]      =  2.0f * Cw[(h * PD + p) * 2 + 0];
    g_W2[h * K2P + PD + p] = -2.0f * Cw[(h * PD + p) * 2 + 1];

    if (h == 0) { g_Lam[2 * p] = lam_re; g_Lam[2 * p + 1] = lam_im; }
}

// ---------------- tf32 mma.sync GEMM: C(M,512) = A(M,512) * W(512,512)^T ----------------
// CTA tile 128x128, BK=16, 8 warps in 2(m) x 4(n), warp tile 64x32.
// smem holds A/B tiles pre-permuted into m16n8k8 fragment order:
//   A block (16m x 8k) = 512B: thread t owns a0..a3 contiguous (one LDS.128)
//   B block (8k x 8n)  = 256B: thread t owns b0,b1 contiguous (one LDS.64)
#define GM 128
#define GN 128
#define GK 16

__device__ __forceinline__ float gelu_tanh(float x) {
    float x3 = x * x * x;
    float t  = tanhf(0.7978845608028654f * (x + 0.044715f * x3));
    return 0.5f * x * (1.0f + t);
}

__device__ __forceinline__ void mma_tf32(float* d, const uint32_t* a, const uint32_t* b) {
    asm volatile(
        "mma.sync.aligned.m16n8k8.row.col.f32.tf32.tf32.f32 "
        "{%0,%1,%2,%3}, {%4,%5,%6,%7}, {%8,%9}, {%0,%1,%2,%3};"
        : "+f"(d[0]), "+f"(d[1]), "+f"(d[2]), "+f"(d[3])
        : "r"(a[0]), "r"(a[1]), "r"(a[2]), "r"(a[3]), "r"(b[0]), "r"(b[1]));
}

template <bool EPI>
__global__ void __launch_bounds__(256, 2) tc_gemm(const float* __restrict__ A,
                                                  const float* __restrict__ W,
                                                  float* __restrict__ C,
                                                  const float* __restrict__ U,
                                                  const float* __restrict__ Dv) {
    // per buffer: A frags 2048 floats (8 mi x 2 ks x 128), B frags 2048 (16 ni x 2 ks x 64)
    __shared__ uint32_t sm[2 * 4096];

    const int tid  = threadIdx.x;
    const int lane = tid & 31, wid = tid >> 5;
    const int wm = wid >> 2, wn = wid & 3;         // warp grid 2 x 4
    const int m0 = blockIdx.y * GM, n0 = blockIdx.x * GN;

    // loader indices (2 float4 each for A and B per thread per tile)
    const int lrow = tid >> 2;          // 0..63 (+64 for i=1)
    const int lc4  = (tid & 3) << 2;    // 0,4,8,12

    float acc[4][4][4];
#pragma unroll
    for (int i = 0; i < 4; i++)
#pragma unroll
        for (int j = 0; j < 4; j++)
#pragma unroll
            for (int k = 0; k < 4; k++) acc[i][j][k] = 0.0f;

    float4 pa[2], pb[2];

    // destination offsets (constant per thread, per i)
    //   A: row r16 = row & 15, mi = row >> 4; base = (ks*8+mi)*128 + (r16&7)*16 + regA
    //   B: nn = row & 7, ni = row >> 3;       base = 2048 + (ks*16+ni)*64 + nn*8 + regB
    const int ksl  = lc4 >> 3;                  // k-step of this float4 (0 or 1)
    const int regA = ((lc4 >> 2) & 1) << 1;     // a2/a3 half if col>=4
    const int regB = (lc4 >> 2) & 1;            // b1 half if k>=4

#define LOAD_TILE(kt)                                                              \
    {                                                                              \
        const float* Ap = A + (size_t)(m0) * 512 + (kt) * GK + lc4;                \
        const float* Wp = W + (size_t)(n0) * 512 + (kt) * GK + lc4;                \
        pa[0] = *(const float4*)(Ap + (size_t)lrow * 512);                         \
        pa[1] = *(const float4*)(Ap + (size_t)(lrow + 64) * 512);                  \
        pb[0] = *(const float4*)(Wp + (size_t)lrow * 512);                         \
        pb[1] = *(const float4*)(Wp + (size_t)(lrow + 64) * 512);                  \
    }

#define STORE_TILE(buf)                                                            \
    {                                                                              \
        uint32_t* S = sm + (buf) * 4096;                                           \
        _Pragma("unroll")                                                          \
        for (int i = 0; i < 2; i++) {                                              \
            int row = lrow + i * 64;                                               \
            int mi = row >> 4, r16 = row & 15;                                     \
            int da = (ksl * 8 + mi) * 128 + (r16 & 7) * 16 + ((r16 >> 3) + regA);  \
            float4 v = pa[i];                                                      \
            S[da + 0]  = f2tf32(v.x); S[da + 4]  = f2tf32(v.y);                    \
            S[da + 8]  = f2tf32(v.z); S[da + 12] = f2tf32(v.w);                    \
            int ni = row >> 3, nn = row & 7;                                       \
            int db = 2048 + (ksl * 16 + ni) * 64 + nn * 8 + regB;                  \
            v = pb[i];                                                             \
            S[db + 0] = f2tf32(v.x); S[db + 2] = f2tf32(v.y);                      \
            S[db + 4] = f2tf32(v.z); S[db + 6] = f2tf32(v.w);                      \
        }                                                                          \
    }

    LOAD_TILE(0);
    STORE_TILE(0);
    __syncthreads();

    for (int kt = 0; kt < 32; kt++) {
        if (kt < 31) LOAD_TILE(kt + 1);

        const uint32_t* S = sm + (kt & 1) * 4096;
#pragma unroll
        for (int ks = 0; ks < 2; ks++) {
            uint4 af[4];
            uint2 bf[4];
#pragma unroll
            for (int mi = 0; mi < 4; mi++)
                af[mi] = *(const uint4*)&S[(ks * 8 + wm * 4 + mi) * 128 + lane * 4];
#pragma unroll
            for (int ni = 0; ni < 4; ni++)
                bf[ni] = *(const uint2*)&S[2048 + (ks * 16 + wn * 4 + ni) * 64 + lane * 2];
#pragma unroll
            for (int mi = 0; mi < 4; mi++)
#pragma unroll
                for (int ni = 0; ni < 4; ni++)
                    mma_tf32(acc[mi][ni], (const uint32_t*)&af[mi], (const uint32_t*)&bf[ni]);
        }

        if (kt < 31) STORE_TILE((kt + 1) & 1);
        __syncthreads();
    }

    // ---- epilogue: c0,c1 at (row, col..col+1); c2,c3 at (row+8, col..col+1) ----
    const int rbase = m0 + wm * 64 + (lane >> 2);
    const int cbase = n0 + wn * 32 + (lane & 3) * 2;
#pragma unroll
    for (int mi = 0; mi < 4; mi++) {
#pragma unroll
        for (int ni = 0; ni < 4; ni++) {
            int row = rbase + mi * 16;
            int col = cbase + ni * 8;
            float2 lo = make_float2(acc[mi][ni][0], acc[mi][ni][1]);
            float2 hi = make_float2(acc[mi][ni][2], acc[mi][ni][3]);
            if (EPI) {
                float d0 = Dv[col], d1 = Dv[col + 1];
                const float* u0 = U + (size_t)row * 512 + col;
                const float* u8 = U + (size_t)(row + 8) * 512 + col;
                lo.x = gelu_tanh(lo.x + d0 * u0[0]);
                lo.y = gelu_tanh(lo.y + d1 * u0[1]);
                hi.x = gelu_tanh(hi.x + d0 * u8[0]);
                hi.y = gelu_tanh(hi.y + d1 * u8[1]);
            }
            *(float2*)(C + (size_t)row * 512 + col)       = lo;
            *(float2*)(C + (size_t)(row + 8) * 512 + col) = hi;
        }
    }
}

// ---------------- chunked scan over L ----------------
__global__ void __launch_bounds__(PD) scan_pass1() {
    int p  = threadIdx.x;
    int bc = blockIdx.x;
    int b = bc / NC, c = bc % NC;
    float lr = g_Lam[2 * p], li = g_Lam[2 * p + 1];
    float sr = 0.0f, si = 0.0f;
    size_t base = ((size_t)b * LEN + (size_t)c * CL) * K2P + p;
#pragma unroll 8
    for (int j = 0; j < CL; j++) {
        float br = g_Bu[base + (size_t)j * K2P];
        float bi = g_Bu[base + (size_t)j * K2P + PD];
        float nr = lr * sr - li * si + br;
        float ni = lr * si + li * sr + bi;
        sr = nr; si = ni;
    }
    int idx = (bc * PD + p) * 2;
    g_csum[idx] = sr; g_csum[idx + 1] = si;
}

__global__ void scan_pass2() {
    int t = blockIdx.x * blockDim.x + threadIdx.x;
    if (t >= BSZ * PD) return;
    int b = t / PD, p = t % PD;
    float lr = g_Lam[2 * p], li = g_Lam[2 * p + 1];
    float ar = 1.0f, ai = 0.0f;
    for (int i = 0; i < CL; i++) {
        float nr = ar * lr - ai * li;
        ai = ar * li + ai * lr; ar = nr;
    }
    float cr = 0.0f, ci = 0.0f;
    int base = (b * NC * PD + p) * 2;
    float nsr = g_csum[base], nsi = g_csum[base + 1];    // prefetch chunk 0
    for (int c = 0; c < NC; c++) {
        float sr = nsr, si = nsi;
        if (c + 1 < NC) {                                 // independent prefetch of c+1
            nsr = g_csum[base + (c + 1) * PD * 2];
            nsi = g_csum[base + (c + 1) * PD * 2 + 1];
        }
        int idx = base + c * PD * 2;
        g_carry[idx] = cr; g_carry[idx + 1] = ci;
        float nr = ar * cr - ai * ci + sr;
        float ni = ar * ci + ai * cr + si;
        cr = nr; ci = ni;
    }
}

__global__ void __launch_bounds__(PD) scan_pass3() {
    int p  = threadIdx.x;
    int bc = blockIdx.x;
    int b = bc / NC, c = bc % NC;
    float lr = g_Lam[2 * p], li = g_Lam[2 * p + 1];
    int cidx = (bc * PD + p) * 2;
    float xr = g_carry[cidx], xi = g_carry[cidx + 1];
    size_t base = ((size_t)b * LEN + (size_t)c * CL) * K2P + p;
#pragma unroll 4
    for (int j = 0; j < CL; j++) {
        float br = g_Bu[base + (size_t)j * K2P];
        float bi = g_Bu[base + (size_t)j * K2P + PD];
        float nr = lr * xr - li * xi + br;
        float ni = lr * xi + li * xr + bi;
        xr = nr; xi = ni;
        g_XS[base + (size_t)j * K2P]      = xr;
        g_XS[base + (size_t)j * K2P + PD] = xi;
    }
}

// ---------------- launch ----------------
extern "C" void kernel_launch(void* const* d_in, const int* in_sizes, int n_in,
                              void* d_out, int out_size) {
    const float* u   = (const float*)d_in[0];
    const float* Lre = (const float*)d_in[1];
    const float* Lim = (const float*)d_in[2];
    const float* Bw  = (const float*)d_in[3];
    const float* Cw  = (const float*)d_in[4];
    const float* Dv  = (const float*)d_in[5];
    const float* ls  = (const float*)d_in[6];
    float* out = (float*)d_out;

    void *pW1, *pW2, *pBu, *pXS;
    cudaGetSymbolAddress(&pW1, g_W1);
    cudaGetSymbolAddress(&pW2, g_W2);
    cudaGetSymbolAddress(&pBu, g_Bu);
    cudaGetSymbolAddress(&pXS, g_XS);

    setup_kernel<<<(PD * HD + 255) / 256, 256>>>(Lre, Lim, Bw, Cw, ls);

    dim3 ggrid(K2P / GN, BL / GM);   // (4, 256)
    tc_gemm<false><<<ggrid, 256>>>(u, (const float*)pW1, (float*)pBu, nullptr, nullptr);

    scan_pass1<<<BSZ * NC, PD>>>();
    scan_pass2<<<(BSZ * PD + 255) / 256, 256>>>();
    scan_pass3<<<BSZ * NC, PD>>>();

    tc_gemm<true><<<ggrid, 256>>>((const float*)pXS, (const float*)pW2, out, u, Dv);
}

// round 9
// speedup vs baseline: 3.7010x; 1.1408x over previous
#include <cuda_runtime.h>
#include <math.h>
#include <stdint.h>

// Problem constants
#define BSZ 8
#define LEN 4096
#define HD  512          // H
#define PD  256          // P
#define BL  (BSZ * LEN)  // 32768 rows
#define K2P 512          // 2*P (re block | im block)
#define NC  64           // scan chunks per sequence
#define CL  (LEN / NC)   // 64 steps per chunk

// ---------------- device scratch (no cudaMalloc allowed) ----------------
__device__ float g_W1[K2P * HD];                 // [2P][H]: Re(B_bar) rows 0..P-1, Im rows P..2P-1
__device__ float g_W2[HD * K2P];                 // [H][2P]: 2*C_re | -2*C_im
__device__ float g_W1f[K2P * HD];                // W1 pre-rounded tf32, B-fragment-permuted
__device__ float g_W2f[HD * K2P];                // W2 pre-rounded tf32, B-fragment-permuted
__device__ float g_Lam[2 * PD];                  // Lambda_bar (re, im)
__device__ float g_Bu[(size_t)BL * K2P];         // (BL, 2P)
__device__ float g_XS[(size_t)BL * K2P];         // (BL, 2P)
__device__ float g_csum[BSZ * NC * PD * 2];
__device__ float g_carry[BSZ * NC * PD * 2];

__device__ __forceinline__ uint32_t f2tf32(float v) {
    uint32_t r;
    asm("cvt.rna.tf32.f32 %0, %1;" : "=r"(r) : "f"(v));
    return r;
}
__device__ __forceinline__ uint32_t smem_u32(const void* p) {
    uint32_t a;
    asm("{ .reg .u64 t; cvta.to.shared.u64 t, %1; cvt.u32.u64 %0, t; }" : "=r"(a) : "l"(p));
    return a;
}

// ---------------- setup: discretization + weight packing ----------------
__global__ void setup_kernel(const float* __restrict__ Lre, const float* __restrict__ Lim,
                             const float* __restrict__ Bw,  const float* __restrict__ Cw,
                             const float* __restrict__ logstep) {
    int idx = blockIdx.x * blockDim.x + threadIdx.x;
    if (idx >= PD * HD) return;
    int p = idx / HD, h = idx % HD;

    float lre = Lre[p], lim = Lim[p];
    float step = expf(logstep[p]);
    float er = expf(lre * step);
    float sb, cb; sincosf(lim * step, &sb, &cb);
    float lam_re = er * cb, lam_im = er * sb;          // Lambda_bar

    float nr = lam_re - 1.0f, ni = lam_im;
    float d2 = lre * lre + lim * lim;
    float cr = (nr * lre + ni * lim) / d2;
    float ci = (ni * lre - nr * lim) / d2;

    float br = Bw[(p * HD + h) * 2 + 0];
    float bi = Bw[(p * HD + h) * 2 + 1];
    g_W1[p * HD + h]        = cr * br - ci * bi;       // Re(B_bar)
    g_W1[(PD + p) * HD + h] = cr * bi + ci * br;       // Im(B_bar)

    g_W2[h * K2P + p]      =  2.0f * Cw[(h * PD + p) * 2 + 0];
    g_W2[h * K2P + PD + p] = -2.0f * Cw[(h * PD + p) * 2 + 1];

    if (h == 0) { g_Lam[2 * p] = lam_re; g_Lam[2 * p + 1] = lam_im; }
}

// ---------------- W permute: standard [n][k] -> B-fragment order (tf32-rounded) ----
// Fragment word w (per n-tile t, per k-tile kt, w in [0,2048)):
//   slot = w&7, nn = (w>>3)&7, blk = w>>6, ksl = blk>>4, ni = blk&15
//   row = ni*8+nn, k = kt*16 + ksl*8 + (slot&1)*4 + (slot>>1)
__global__ void permute_W() {
    int idx = blockIdx.x * blockDim.x + threadIdx.x;   // [0, 2*512*512)
    int mat   = idx >> 18;                 // 0: W1, 1: W2
    int w_all = idx & 262143;
    int t   = w_all >> 16;                 // n-tile 0..3
    int rem = w_all & 65535;
    int kt  = rem >> 11;                   // 0..31
    int w   = rem & 2047;
    int slot = w & 7, nn = (w >> 3) & 7, blk = w >> 6;
    int ksl = blk >> 4, ni = blk & 15;
    int row = ni * 8 + nn;
    int k = kt * 16 + ksl * 8 + (slot & 1) * 4 + (slot >> 1);
    const float* src = mat ? g_W2 : g_W1;
    float* dst = mat ? g_W2f : g_W1f;
    dst[w_all] = __uint_as_float(f2tf32(src[(size_t)(t * 128 + row) * 512 + k]));
}

// ---------------- tf32 mma.sync GEMM: C(M,512) = A(M,512) * W(512,512)^T ----------------
// CTA tile 128x128, BK=16, 8 warps in 2(m) x 4(n), warp tile 64x32.
// A staged via register permute (+tf32 RNA cvt); B streamed with cp.async from
// the pre-permuted g_Wf (already tf32).
#define GM 128
#define GN 128
#define GK 16

__device__ __forceinline__ float gelu_tanh(float x) {
    float x3 = x * x * x;
    float t  = tanhf(0.7978845608028654f * (x + 0.044715f * x3));
    return 0.5f * x * (1.0f + t);
}

__device__ __forceinline__ void mma_tf32(float* d, const uint32_t* a, const uint32_t* b) {
    asm volatile(
        "mma.sync.aligned.m16n8k8.row.col.f32.tf32.tf32.f32 "
        "{%0,%1,%2,%3}, {%4,%5,%6,%7}, {%8,%9}, {%0,%1,%2,%3};"
        : "+f"(d[0]), "+f"(d[1]), "+f"(d[2]), "+f"(d[3])
        : "r"(a[0]), "r"(a[1]), "r"(a[2]), "r"(a[3]), "r"(b[0]), "r"(b[1]));
}

template <bool EPI>
__global__ void __launch_bounds__(256, 2) tc_gemm(const float* __restrict__ A,
                                                  const float* __restrict__ Wf,
                                                  float* __restrict__ C,
                                                  const float* __restrict__ U,
                                                  const float* __restrict__ Dv) {
    // sm: A frags 2 bufs x 2048 words, then B frags 2 bufs x 2048 words
    __shared__ uint32_t sm[4 * 2048];

    const int tid  = threadIdx.x;
    const int lane = tid & 31, wid = tid >> 5;
    const int wm = wid >> 2, wn = wid & 3;         // warp grid 2 x 4
    const int m0 = blockIdx.y * GM;
    const int tn = blockIdx.x;                     // n-tile index
    const int n0 = tn * GN;

    const uint32_t sbase = smem_u32(sm);
    // per-thread cp.async dst/src for B: 8 words = 2 x 16B
    const float* wsrc = Wf + (size_t)tn * 65536 + (size_t)tid * 8;

    // loader indices for A (2 float4 per thread per tile)
    const int lrow = tid >> 2;          // 0..63 (+64 for i=1)
    const int lc4  = (tid & 3) << 2;    // 0,4,8,12
    const int ksl  = lc4 >> 3;
    const int regA = ((lc4 >> 2) & 1) << 1;

    float acc[4][4][4];
#pragma unroll
    for (int i = 0; i < 4; i++)
#pragma unroll
        for (int j = 0; j < 4; j++)
#pragma unroll
            for (int k = 0; k < 4; k++) acc[i][j][k] = 0.0f;

    float4 pa[2];

#define CPASYNC_B(kt, buf)                                                          \
    {                                                                               \
        uint32_t d0 = sbase + (uint32_t)(4096 + (buf) * 2048 + tid * 8) * 4u;       \
        const float* s0 = wsrc + (size_t)(kt) * 2048;                               \
        asm volatile("cp.async.ca.shared.global [%0], [%1], 16;" :: "r"(d0), "l"(s0)); \
        asm volatile("cp.async.ca.shared.global [%0], [%1], 16;" :: "r"(d0 + 16), "l"(s0 + 4)); \
        asm volatile("cp.async.commit_group;");                                     \
    }

#define LOAD_A(kt)                                                                  \
    {                                                                               \
        const float* Ap = A + (size_t)(m0) * 512 + (kt) * GK + lc4;                 \
        pa[0] = *(const float4*)(Ap + (size_t)lrow * 512);                          \
        pa[1] = *(const float4*)(Ap + (size_t)(lrow + 64) * 512);                   \
    }

#define STORE_A(buf)                                                                \
    {                                                                               \
        uint32_t* S = sm + (buf) * 2048;                                            \
        _Pragma("unroll")                                                           \
        for (int i = 0; i < 2; i++) {                                               \
            int row = lrow + i * 64;                                                \
            int mi = row >> 4, r16 = row & 15;                                      \
            int da = (ksl * 8 + mi) * 128 + (r16 & 7) * 16 + ((r16 >> 3) + regA);   \
            float4 v = pa[i];                                                       \
            S[da + 0]  = f2tf32(v.x); S[da + 4]  = f2tf32(v.y);                     \
            S[da + 8]  = f2tf32(v.z); S[da + 12] = f2tf32(v.w);                     \
        }                                                                           \
    }

    CPASYNC_B(0, 0);
    LOAD_A(0);
    STORE_A(0);
    asm volatile("cp.async.wait_group 0;" ::: "memory");
    __syncthreads();

    for (int kt = 0; kt < 32; kt++) {
        if (kt < 31) {
            CPASYNC_B(kt + 1, (kt + 1) & 1);
            LOAD_A(kt + 1);
        }

        const uint32_t* SA = sm + (kt & 1) * 2048;
        const uint32_t* SB = sm + 4096 + (kt & 1) * 2048;
#pragma unroll
        for (int ks = 0; ks < 2; ks++) {
            uint4 af[4];
            uint2 bf[4];
#pragma unroll
            for (int mi = 0; mi < 4; mi++)
                af[mi] = *(const uint4*)&SA[(ks * 8 + wm * 4 + mi) * 128 + lane * 4];
#pragma unroll
            for (int ni = 0; ni < 4; ni++)
                bf[ni] = *(const uint2*)&SB[(ks * 16 + wn * 4 + ni) * 64 + lane * 2];
#pragma unroll
            for (int mi = 0; mi < 4; mi++)
#pragma unroll
                for (int ni = 0; ni < 4; ni++)
                    mma_tf32(acc[mi][ni], (const uint32_t*)&af[mi], (const uint32_t*)&bf[ni]);
        }

        if (kt < 31) STORE_A((kt + 1) & 1);
        asm volatile("cp.async.wait_group 0;" ::: "memory");
        __syncthreads();
    }

    // ---- epilogue: c0,c1 at (row, col..col+1); c2,c3 at (row+8, col..col+1) ----
    const int rbase = m0 + wm * 64 + (lane >> 2);
    const int cbase = n0 + wn * 32 + (lane & 3) * 2;
#pragma unroll
    for (int mi = 0; mi < 4; mi++) {
#pragma unroll
        for (int ni = 0; ni < 4; ni++) {
            int row = rbase + mi * 16;
            int col = cbase + ni * 8;
            float2 lo = make_float2(acc[mi][ni][0], acc[mi][ni][1]);
            float2 hi = make_float2(acc[mi][ni][2], acc[mi][ni][3]);
            if (EPI) {
                float d0 = Dv[col], d1 = Dv[col + 1];
                const float* u0 = U + (size_t)row * 512 + col;
                const float* u8 = U + (size_t)(row + 8) * 512 + col;
                lo.x = gelu_tanh(lo.x + d0 * u0[0]);
                lo.y = gelu_tanh(lo.y + d1 * u0[1]);
                hi.x = gelu_tanh(hi.x + d0 * u8[0]);
                hi.y = gelu_tanh(hi.y + d1 * u8[1]);
            }
            *(float2*)(C + (size_t)row * 512 + col)       = lo;
            *(float2*)(C + (size_t)(row + 8) * 512 + col) = hi;
        }
    }
}

// ---------------- chunked scan over L ----------------
__global__ void __launch_bounds__(PD) scan_pass1() {
    int p  = threadIdx.x;
    int bc = blockIdx.x;
    int b = bc / NC, c = bc % NC;
    float lr = g_Lam[2 * p], li = g_Lam[2 * p + 1];
    float sr = 0.0f, si = 0.0f;
    size_t base = ((size_t)b * LEN + (size_t)c * CL) * K2P + p;
#pragma unroll 8
    for (int j = 0; j < CL; j++) {
        float br = g_Bu[base + (size_t)j * K2P];
        float bi = g_Bu[base + (size_t)j * K2P + PD];
        float nr = lr * sr - li * si + br;
        float ni = lr * si + li * sr + bi;
        sr = nr; si = ni;
    }
    int idx = (bc * PD + p) * 2;
    g_csum[idx] = sr; g_csum[idx + 1] = si;
}

__global__ void __launch_bounds__(64) scan_pass2() {
    int t = blockIdx.x * blockDim.x + threadIdx.x;
    if (t >= BSZ * PD) return;
    int b = t / PD, p = t % PD;
    float lr = g_Lam[2 * p], li = g_Lam[2 * p + 1];
    float ar = 1.0f, ai = 0.0f;
    for (int i = 0; i < CL; i++) {
        float nr = ar * lr - ai * li;
        ai = ar * li + ai * lr; ar = nr;
    }
    float cr = 0.0f, ci = 0.0f;
    int base = (b * NC * PD + p) * 2;
    for (int c0 = 0; c0 < NC; c0 += 8) {
        float2 s[8];
#pragma unroll
        for (int j = 0; j < 8; j++) {           // MLP=8 batch prefetch
            s[j].x = g_csum[base + (c0 + j) * PD * 2];
            s[j].y = g_csum[base + (c0 + j) * PD * 2 + 1];
        }
#pragma unroll
        for (int j = 0; j < 8; j++) {
            int idx = base + (c0 + j) * PD * 2;
            g_carry[idx] = cr; g_carry[idx + 1] = ci;
            float nr = ar * cr - ai * ci + s[j].x;
            float ni = ar * ci + ai * cr + s[j].y;
            cr = nr; ci = ni;
        }
    }
}

__global__ void __launch_bounds__(PD) scan_pass3() {
    int p  = threadIdx.x;
    int bc = blockIdx.x;
    int b = bc / NC, c = bc % NC;
    float lr = g_Lam[2 * p], li = g_Lam[2 * p + 1];
    int cidx = (bc * PD + p) * 2;
    float xr = g_carry[cidx], xi = g_carry[cidx + 1];
    size_t base = ((size_t)b * LEN + (size_t)c * CL) * K2P + p;
#pragma unroll 4
    for (int j = 0; j < CL; j++) {
        float br = g_Bu[base + (size_t)j * K2P];
        float bi = g_Bu[base + (size_t)j * K2P + PD];
        float nr = lr * xr - li * xi + br;
        float ni = lr * xi + li * xr + bi;
        xr = nr; xi = ni;
        g_XS[base + (size_t)j * K2P]      = xr;
        g_XS[base + (size_t)j * K2P + PD] = xi;
    }
}

// ---------------- launch ----------------
extern "C" void kernel_launch(void* const* d_in, const int* in_sizes, int n_in,
                              void* d_out, int out_size) {
    const float* u   = (const float*)d_in[0];
    const float* Lre = (const float*)d_in[1];
    const float* Lim = (const float*)d_in[2];
    const float* Bw  = (const float*)d_in[3];
    const float* Cw  = (const float*)d_in[4];
    const float* Dv  = (const float*)d_in[5];
    const float* ls  = (const float*)d_in[6];
    float* out = (float*)d_out;

    void *pW1f, *pW2f, *pBu, *pXS;
    cudaGetSymbolAddress(&pW1f, g_W1f);
    cudaGetSymbolAddress(&pW2f, g_W2f);
    cudaGetSymbolAddress(&pBu, g_Bu);
    cudaGetSymbolAddress(&pXS, g_XS);

    setup_kernel<<<(PD * HD + 255) / 256, 256>>>(Lre, Lim, Bw, Cw, ls);
    permute_W<<<(2 * 512 * 512) / 256, 256>>>();

    dim3 ggrid(K2P / GN, BL / GM);   // (4, 256)
    tc_gemm<false><<<ggrid, 256>>>(u, (const float*)pW1f, (float*)pBu, nullptr, nullptr);

    scan_pass1<<<BSZ * NC, PD>>>();
    scan_pass2<<<(BSZ * PD + 63) / 64, 64>>>();
    scan_pass3<<<BSZ * NC, PD>>>();

    tc_gemm<true><<<ggrid, 256>>>((const float*)pXS, (const float*)pW2f, out, u, Dv);
}

// round 11
// speedup vs baseline: 4.0111x; 1.0838x over previous
#include <cuda_runtime.h>
#include <math.h>
#include <stdint.h>

// Problem constants
#define BSZ 8
#define LEN 4096
#define HD  512          // H
#define PD  256          // P
#define BL  (BSZ * LEN)  // 32768 rows
#define K2P 512          // 2*P (re block | im block)
#define NC  64           // scan chunks per sequence
#define CL  (LEN / NC)   // 64 steps per chunk

// ---------------- device scratch (no cudaMalloc allowed) ----------------
__device__ float g_W1[K2P * HD];                 // [2P][H]
__device__ float g_W2[HD * K2P];                 // [H][2P]
__device__ float g_W1f[K2P * HD];                // W1 tf32, B-fragment-permuted
__device__ float g_W2f[HD * K2P];                // W2 tf32, B-fragment-permuted
__device__ float g_Lam[2 * PD];                  // Lambda_bar (re, im)
__device__ float g_Bu[(size_t)BL * K2P];         // (BL, 2P)
__device__ float g_XSf[(size_t)BL * K2P];        // scan states, tf32 + A-fragment-permuted
__device__ float g_csum[BSZ * NC * PD * 2];
__device__ float g_carry[BSZ * NC * PD * 2];

__device__ __forceinline__ uint32_t f2tf32(float v) {
    uint32_t r;
    asm("cvt.rna.tf32.f32 %0, %1;" : "=r"(r) : "f"(v));
    return r;
}
__device__ __forceinline__ uint32_t smem_u32(const void* p) {
    uint32_t a;
    asm("{ .reg .u64 t; cvta.to.shared.u64 t, %1; cvt.u32.u64 %0, t; }" : "=r"(a) : "l"(p));
    return a;
}

// A-fragment word index within a (128row x 16k) tile of 2048 words:
//   w16(k) = (k>>3)*8 + ((k&3)*2) + ((k&7)>>2), physical = row*16 + (w16 ^ ((row&7)<<1))
__device__ __forceinline__ int a_word(int row128, int k16) {
    int ksl = k16 >> 3, kk = k16 & 7;
    int w = ksl * 8 + (kk & 3) * 2 + (kk >> 2);
    return row128 * 16 + (w ^ ((row128 & 7) << 1));
}

// ---------------- setup: discretization + weight packing ----------------
__global__ void setup_kernel(const float* __restrict__ Lre, const float* __restrict__ Lim,
                             const float* __restrict__ Bw,  const float* __restrict__ Cw,
                             const float* __restrict__ logstep) {
    int idx = blockIdx.x * blockDim.x + threadIdx.x;
    if (idx >= PD * HD) return;
    int p = idx / HD, h = idx % HD;

    float lre = Lre[p], lim = Lim[p];
    float step = expf(logstep[p]);
    float er = expf(lre * step);
    float sb, cb; sincosf(lim * step, &sb, &cb);
    float lam_re = er * cb, lam_im = er * sb;          // Lambda_bar

    float nr = lam_re - 1.0f, ni = lam_im;
    float d2 = lre * lre + lim * lim;
    float cr = (nr * lre + ni * lim) / d2;
    float ci = (ni * lre - nr * lim) / d2;

    float br = Bw[(p * HD + h) * 2 + 0];
    float bi = Bw[(p * HD + h) * 2 + 1];
    g_W1[p * HD + h]        = cr * br - ci * bi;       // Re(B_bar)
    g_W1[(PD + p) * HD + h] = cr * bi + ci * br;       // Im(B_bar)

    g_W2[h * K2P + p]      =  2.0f * Cw[(h * PD + p) * 2 + 0];
    g_W2[h * K2P + PD + p] = -2.0f * Cw[(h * PD + p) * 2 + 1];

    if (h == 0) { g_Lam[2 * p] = lam_re; g_Lam[2 * p + 1] = lam_im; }
}

// ---------------- W permute: [n][k] -> B-fragment order (tf32-rounded) ----------------
__global__ void permute_W() {
    int idx = blockIdx.x * blockDim.x + threadIdx.x;   // [0, 2*512*512)
    int mat   = idx >> 18;
    int w_all = idx & 262143;
    int t   = w_all >> 16;                 // n-tile 0..3
    int rem = w_all & 65535;
    int kt  = rem >> 11;                   // 0..31
    int w   = rem & 2047;
    int slot = w & 7, nn = (w >> 3) & 7, blk = w >> 6;
    int ksl = blk >> 4, ni = blk & 15;
    int row = ni * 8 + nn;
    int k = kt * 16 + ksl * 8 + (slot & 1) * 4 + (slot >> 1);
    const float* src = mat ? g_W2 : g_W1;
    float* dst = mat ? g_W2f : g_W1f;
    dst[w_all] = __uint_as_float(f2tf32(src[(size_t)(t * 128 + row) * 512 + k]));
}

// ---------------- common GEMM pieces ----------------
#define GM 128
#define GN 128
#define GK 16

__device__ __forceinline__ float gelu_tanh(float x) {
    float x3 = x * x * x;
    float t  = tanhf(0.7978845608028654f * (x + 0.044715f * x3));
    return 0.5f * x * (1.0f + t);
}

__device__ __forceinline__ void mma_tf32(float* d, const uint32_t* a, const uint32_t* b) {
    asm volatile(
        "mma.sync.aligned.m16n8k8.row.col.f32.tf32.tf32.f32 "
        "{%0,%1,%2,%3}, {%4,%5,%6,%7}, {%8,%9}, {%0,%1,%2,%3};"
        : "+f"(d[0]), "+f"(d[1]), "+f"(d[2]), "+f"(d[3])
        : "r"(a[0]), "r"(a[1]), "r"(a[2]), "r"(a[3]), "r"(b[0]), "r"(b[1]));
}

// fragment compute for one k-tile: SA = A frags (2048 words), SB = B frags (2048 words)
__device__ __forceinline__ void compute_tile(const uint32_t* SA, const uint32_t* SB,
                                             int wm, int wn, int lane,
                                             float acc[4][4][4]) {
    const int rA = lane >> 2, cA = lane & 3;
    const int swA = rA << 1;
#pragma unroll
    for (int ks = 0; ks < 2; ks++) {
        uint32_t af[4][4];
        uint2 bf[4];
#pragma unroll
        for (int mi = 0; mi < 4; mi++) {
            int wlo = (wm * 64 + mi * 16 + rA) * 16 + ((ks * 8 + cA * 2) ^ swA);
            uint2 lo = *(const uint2*)&SA[wlo];
            uint2 hi = *(const uint2*)&SA[wlo + 128];
            af[mi][0] = lo.x; af[mi][1] = hi.x; af[mi][2] = lo.y; af[mi][3] = hi.y;
        }
#pragma unroll
        for (int ni = 0; ni < 4; ni++)
            bf[ni] = *(const uint2*)&SB[(ks * 16 + wn * 4 + ni) * 64 + lane * 2];
#pragma unroll
        for (int mi = 0; mi < 4; mi++)
#pragma unroll
            for (int ni = 0; ni < 4; ni++)
                mma_tf32(acc[mi][ni], af[mi], (const uint32_t*)&bf[ni]);
    }
}

// ---------------- GEMM1: Bu = u * W1^T (inline A permute+cvt, B cp.async) ----------------
__global__ void __launch_bounds__(256, 2) tc_gemm1(const float* __restrict__ A,
                                                   const float* __restrict__ Wf,
                                                   float* __restrict__ C) {
    __shared__ __align__(16) uint32_t sm[4 * 2048];   // A bufs 0,2048; B bufs 4096,6144

    const int tid  = threadIdx.x;
    const int lane = tid & 31, wid = tid >> 5;
    const int wm = wid >> 2, wn = wid & 3;
    const int m0 = blockIdx.y * GM;
    const int tn = blockIdx.x;
    const int n0 = tn * GN;

    const uint32_t sbase = smem_u32(sm);
    const float* wsrc = Wf + (size_t)tn * 65536 + (size_t)tid * 8;

    const int lrow = tid >> 2;
    const int lc4  = (tid & 3) << 2;
    const int w0A  = ((lc4 >> 3) << 3) + ((lc4 & 4) >> 2);   // base w16 for this float4

    float acc[4][4][4];
#pragma unroll
    for (int i = 0; i < 4; i++)
#pragma unroll
        for (int j = 0; j < 4; j++)
#pragma unroll
            for (int k = 0; k < 4; k++) acc[i][j][k] = 0.0f;

    float4 pa[2];

#define CPASYNC_B(kt, buf)                                                            \
    {                                                                                 \
        uint32_t d0 = sbase + (uint32_t)(4096 + (buf) * 2048 + tid * 8) * 4u;         \
        const float* s0 = wsrc + (size_t)(kt) * 2048;                                 \
        asm volatile("cp.async.ca.shared.global [%0], [%1], 16;" :: "r"(d0), "l"(s0));\
        asm volatile("cp.async.ca.shared.global [%0], [%1], 16;" :: "r"(d0 + 16), "l"(s0 + 4)); \
        asm volatile("cp.async.commit_group;");                                       \
    }

#define LOAD_A(kt)                                                                    \
    {                                                                                 \
        const float* Ap = A + (size_t)(m0) * 512 + (kt) * GK + lc4;                   \
        pa[0] = *(const float4*)(Ap + (size_t)lrow * 512);                            \
        pa[1] = *(const float4*)(Ap + (size_t)(lrow + 64) * 512);                     \
    }

#define STORE_A(buf)                                                                  \
    {                                                                                 \
        uint32_t* S = sm + (buf) * 2048;                                              \
        _Pragma("unroll")                                                             \
        for (int i = 0; i < 2; i++) {                                                 \
            int row = lrow + i * 64;                                                  \
            int rb = row * 16, sw = (row & 7) << 1;                                   \
            float4 v = pa[i];                                                         \
            S[rb + ((w0A + 0) ^ sw)] = f2tf32(v.x);                                   \
            S[rb + ((w0A + 2) ^ sw)] = f2tf32(v.y);                                   \
            S[rb + ((w0A + 4) ^ sw)] = f2tf32(v.z);                                   \
            S[rb + ((w0A + 6) ^ sw)] = f2tf32(v.w);                                   \
        }                                                                             \
    }

    CPASYNC_B(0, 0);
    LOAD_A(0);
    STORE_A(0);
    asm volatile("cp.async.wait_group 0;" ::: "memory");
    __syncthreads();

    for (int kt = 0; kt < 32; kt++) {
        if (kt < 31) {
            CPASYNC_B(kt + 1, (kt + 1) & 1);
            LOAD_A(kt + 1);
        }

        compute_tile(sm + (kt & 1) * 2048, sm + 4096 + (kt & 1) * 2048,
                     wm, wn, lane, acc);

        if (kt < 31) STORE_A((kt + 1) & 1);
        asm volatile("cp.async.wait_group 0;" ::: "memory");
        __syncthreads();
    }

    const int rbase = m0 + wm * 64 + (lane >> 2);
    const int cbase = n0 + wn * 32 + (lane & 3) * 2;
#pragma unroll
    for (int mi = 0; mi < 4; mi++)
#pragma unroll
        for (int ni = 0; ni < 4; ni++) {
            int row = rbase + mi * 16, col = cbase + ni * 8;
            *(float2*)(C + (size_t)row * 512 + col) =
                make_float2(acc[mi][ni][0], acc[mi][ni][1]);
            *(float2*)(C + (size_t)(row + 8) * 512 + col) =
                make_float2(acc[mi][ni][2], acc[mi][ni][3]);
        }
}

// ---------------- GEMM2: out = gelu(XS * W2^T + D*u); both operands cp.async, 3-stage ----
__global__ void __launch_bounds__(256, 2) tc_gemm2(const float* __restrict__ Af,
                                                   const float* __restrict__ Wf,
                                                   float* __restrict__ C,
                                                   const float* __restrict__ U,
                                                   const float* __restrict__ Dv) {
    __shared__ __align__(16) uint32_t sm[3 * 4096];   // stage s: A at s*4096, B at s*4096+2048

    const int tid  = threadIdx.x;
    const int lane = tid & 31, wid = tid >> 5;
    const int wm = wid >> 2, wn = wid & 3;
    const int mt = blockIdx.y;
    const int m0 = mt * GM;
    const int tn = blockIdx.x;
    const int n0 = tn * GN;

    const uint32_t sbase = smem_u32(sm);
    const float* asrc = Af + (size_t)mt * 65536 + (size_t)tid * 8;
    const float* wsrc = Wf + (size_t)tn * 65536 + (size_t)tid * 8;

    float acc[4][4][4];
#pragma unroll
    for (int i = 0; i < 4; i++)
#pragma unroll
        for (int j = 0; j < 4; j++)
#pragma unroll
            for (int k = 0; k < 4; k++) acc[i][j][k] = 0.0f;

#define ISSUE2(kt, st)                                                                \
    {                                                                                 \
        uint32_t da = sbase + (uint32_t)((st) * 4096 + tid * 8) * 4u;                 \
        const float* sa = asrc + (size_t)(kt) * 2048;                                 \
        asm volatile("cp.async.ca.shared.global [%0], [%1], 16;" :: "r"(da), "l"(sa));\
        asm volatile("cp.async.ca.shared.global [%0], [%1], 16;" :: "r"(da + 16), "l"(sa + 4)); \
        uint32_t db = da + 2048u * 4u;                                                \
        const float* sb2 = wsrc + (size_t)(kt) * 2048;                                \
        asm volatile("cp.async.ca.shared.global [%0], [%1], 16;" :: "r"(db), "l"(sb2));\
        asm volatile("cp.async.ca.shared.global [%0], [%1], 16;" :: "r"(db + 16), "l"(sb2 + 4)); \
        asm volatile("cp.async.commit_group;");                                       \
    }

    ISSUE2(0, 0);
    ISSUE2(1, 1);

    int st = 0, sti = 2;
    for (int kt = 0; kt < 32; kt++) {
        if (kt < 31) { asm volatile("cp.async.wait_group 1;" ::: "memory"); }
        else         { asm volatile("cp.async.wait_group 0;" ::: "memory"); }
        __syncthreads();
        if (kt < 30) {
            ISSUE2(kt + 2, sti);
            sti = (sti == 2) ? 0 : sti + 1;
        }

        compute_tile(sm + st * 4096, sm + st * 4096 + 2048, wm, wn, lane, acc);
        st = (st == 2) ? 0 : st + 1;
    }

    const int rbase = m0 + wm * 64 + (lane >> 2);
    const int cbase = n0 + wn * 32 + (lane & 3) * 2;
#pragma unroll
    for (int mi = 0; mi < 4; mi++)
#pragma unroll
        for (int ni = 0; ni < 4; ni++) {
            int row = rbase + mi * 16, col = cbase + ni * 8;
            float d0 = Dv[col], d1 = Dv[col + 1];
            const float* u0 = U + (size_t)row * 512 + col;
            const float* u8 = U + (size_t)(row + 8) * 512 + col;
            float2 lo, hi;
            lo.x = gelu_tanh(acc[mi][ni][0] + d0 * u0[0]);
            lo.y = gelu_tanh(acc[mi][ni][1] + d1 * u0[1]);
            hi.x = gelu_tanh(acc[mi][ni][2] + d0 * u8[0]);
            hi.y = gelu_tanh(acc[mi][ni][3] + d1 * u8[1]);
            *(float2*)(C + (size_t)row * 512 + col)       = lo;
            *(float2*)(C + (size_t)(row + 8) * 512 + col) = hi;
        }
}

// ---------------- chunked scan over L ----------------
__global__ void __launch_bounds__(PD) scan_pass1() {
    int p  = threadIdx.x;
    int bc = blockIdx.x;
    int b = bc / NC, c = bc % NC;
    float lr = g_Lam[2 * p], li = g_Lam[2 * p + 1];
    float sr = 0.0f, si = 0.0f;
    size_t base = ((size_t)b * LEN + (size_t)c * CL) * K2P + p;
#pragma unroll 8
    for (int j = 0; j < CL; j++) {
        float br = g_Bu[base + (size_t)j * K2P];
        float bi = g_Bu[base + (size_t)j * K2P + PD];
        float nr = lr * sr - li * si + br;
        float ni = lr * si + li * sr + bi;
        sr = nr; si = ni;
    }
    int idx = (bc * PD + p) * 2;
    g_csum[idx] = sr; g_csum[idx + 1] = si;
}

__global__ void __launch_bounds__(64) scan_pass2() {
    int t = blockIdx.x * blockDim.x + threadIdx.x;
    if (t >= BSZ * PD) return;
    int b = t / PD, p = t % PD;
    float lr = g_Lam[2 * p], li = g_Lam[2 * p + 1];
    float ar = 1.0f, ai = 0.0f;
    for (int i = 0; i < CL; i++) {
        float nr = ar * lr - ai * li;
        ai = ar * li + ai * lr; ar = nr;
    }
    float cr = 0.0f, ci = 0.0f;
    int base = (b * NC * PD + p) * 2;
    for (int c0 = 0; c0 < NC; c0 += 8) {
        float2 s[8];
#pragma unroll
        for (int j = 0; j < 8; j++) {
            s[j].x = g_csum[base + (c0 + j) * PD * 2];
            s[j].y = g_csum[base + (c0 + j) * PD * 2 + 1];
        }
#pragma unroll
        for (int j = 0; j < 8; j++) {
            int idx = base + (c0 + j) * PD * 2;
            g_carry[idx] = cr; g_carry[idx + 1] = ci;
            float nr = ar * cr - ai * ci + s[j].x;
            float ni = ar * ci + ai * cr + s[j].y;
            cr = nr; ci = ni;
        }
    }
}

// pass3: recurrence + write XS tf32-rounded in A-fragment-permuted layout
__global__ void __launch_bounds__(PD) scan_pass3() {
    int p  = threadIdx.x;
    int bc = blockIdx.x;
    int b = bc / NC, c = bc % NC;
    float lr = g_Lam[2 * p], li = g_Lam[2 * p + 1];
    int cidx = (bc * PD + p) * 2;
    float xr = g_carry[cidx], xi = g_carry[cidx + 1];
    size_t base = ((size_t)b * LEN + (size_t)c * CL) * K2P + p;

    // per-thread constant parts of the permuted address, for k=p and k=PD+p
    int kre = p, kim = PD + p;
    int kt_re = kre >> 4, kt_im = kim >> 4;
    int k16_re = kre & 15, k16_im = kim & 15;    // equal, but keep generic
    int wre = ((k16_re >> 3) << 3) + ((k16_re & 3) << 1) + ((k16_re & 7) >> 2);
    int wim = ((k16_im >> 3) << 3) + ((k16_im & 3) << 1) + ((k16_im & 7) >> 2);

#pragma unroll 4
    for (int j = 0; j < CL; j++) {
        float br = g_Bu[base + (size_t)j * K2P];
        float bi = g_Bu[base + (size_t)j * K2P + PD];
        float nr = lr * xr - li * xi + br;
        float ni = lr * xi + li * xr + bi;
        xr = nr; xi = ni;

        int row = b * LEN + c * CL + j;
        int mt = row >> 7, r128 = row & 127;
        int sw = (r128 & 7) << 1;
        size_t tbase = (size_t)(mt * 32) * 2048 + (size_t)r128 * 16;
        g_XSf[tbase + (size_t)kt_re * 2048 + (wre ^ sw)] = __uint_as_float(f2tf32(xr));
        g_XSf[tbase + (size_t)kt_im * 2048 + (wim ^ sw)] = __uint_as_float(f2tf32(xi));
    }
}

// ---------------- launch ----------------
extern "C" void kernel_launch(void* const* d_in, const int* in_sizes, int n_in,
                              void* d_out, int out_size) {
    const float* u   = (const float*)d_in[0];
    const float* Lre = (const float*)d_in[1];
    const float* Lim = (const float*)d_in[2];
    const float* Bw  = (const float*)d_in[3];
    const float* Cw  = (const float*)d_in[4];
    const float* Dv  = (const float*)d_in[5];
    const float* ls  = (const float*)d_in[6];
    float* out = (float*)d_out;

    void *pW1f, *pW2f, *pBu, *pXSf;
    cudaGetSymbolAddress(&pW1f, g_W1f);
    cudaGetSymbolAddress(&pW2f, g_W2f);
    cudaGetSymbolAddress(&pBu, g_Bu);
    cudaGetSymbolAddress(&pXSf, g_XSf);

    setup_kernel<<<(PD * HD + 255) / 256, 256>>>(Lre, Lim, Bw, Cw, ls);
    permute_W<<<(2 * 512 * 512) / 256, 256>>>();

    dim3 ggrid(K2P / GN, BL / GM);   // (4, 256)
    tc_gemm1<<<ggrid, 256>>>(u, (const float*)pW1f, (float*)pBu);

    scan_pass1<<<BSZ * NC, PD>>>();
    scan_pass2<<<(BSZ * PD + 63) / 64, 64>>>();
    scan_pass3<<<BSZ * NC, PD>>>();

    tc_gemm2<<<ggrid, 256>>>((const float*)pXSf, (const float*)pW2f, out, u, Dv);
}